// round 1
// baseline (speedup 1.0000x reference)
#include <cuda_runtime.h>
#include <math.h>

#define C 100          // number of classes (static in reference)
#define D 256          // feature dim
#define SLICE 32       // dims handled per warp in accumulate pass
#define NSLICES (D / SLICE)   // 8
#define ACC_WARPS 2    // warps per accumulate block (smem = 2*100*32*4 = 25.6KB, static)
#define GY 148         // row chunks -> 8*148 = 1184 blocks = 1 full wave at 8 blocks/SM

__device__ float g_sums[C * D];
__device__ float g_counts[C];
__device__ float g_centers[C * D];
__device__ int   g_label_is_i64;   // 1 => labels are int64 (stride-2 int32 words)

// ---------------------------------------------------------------------------
// Kernel 0: zero scratch + init dtype flag (assume int64 until proven int32)
// ---------------------------------------------------------------------------
__global__ void k_zero() {
    int i = blockIdx.x * blockDim.x + threadIdx.x;
    if (i < C * D) g_sums[i] = 0.0f;
    if (i < C)     g_counts[i] = 0.0f;
    if (i == 0)    g_label_is_i64 = 1;
}

// ---------------------------------------------------------------------------
// Kernel 1: dtype detect. Reading the first N int32 words is safe for both
// layouts (int32 buffer = N words; int64 buffer = 2N words). If labels are
// little-endian int64 with values < 2^31, every odd word is a zero high-half.
// If int32, odd words are labels (uniform 0..99) and are nonzero somewhere
// among 250K samples with certainty.
// ---------------------------------------------------------------------------
__global__ void k_detect(const unsigned int* __restrict__ lw, int nwords) {
    int i = blockIdx.x * blockDim.x + threadIdx.x;
    int idx = 2 * i + 1;
    if (idx < nwords && lw[idx] != 0u) g_label_is_i64 = 0;
}

__device__ __forceinline__ int load_label(const int* __restrict__ l32, int i, int is64) {
    return l32[is64 ? (i << 1) : i];
}

// ---------------------------------------------------------------------------
// Kernel 2: label histogram -> g_counts (float)
// ---------------------------------------------------------------------------
__global__ void k_count(const int* __restrict__ l32, int N) {
    __shared__ int h[C];
    for (int i = threadIdx.x; i < C; i += blockDim.x) h[i] = 0;
    __syncthreads();
    int is64 = g_label_is_i64;
    for (int i = blockIdx.x * blockDim.x + threadIdx.x; i < N;
         i += gridDim.x * blockDim.x) {
        atomicAdd(&h[load_label(l32, i, is64)], 1);
    }
    __syncthreads();
    for (int i = threadIdx.x; i < C; i += blockDim.x)
        if (h[i]) atomicAdd(&g_counts[i], (float)h[i]);
}

// ---------------------------------------------------------------------------
// Kernel 3: segment-sum of feat into g_sums.
// Grid: (NSLICES, GY). Block: 64 threads = 2 warps. Each warp owns a private
// smem accumulator acc[warp][C][SLICE]; lane l handles dim slice*32 + l.
// Bank index = (class*32 + l) % 32 = l  -> conflict-free RMW.
// ---------------------------------------------------------------------------
__global__ void __launch_bounds__(ACC_WARPS * 32)
k_accum(const float* __restrict__ feat, const int* __restrict__ l32,
        int N, int rows_per_block) {
    __shared__ float acc[ACC_WARPS][C][SLICE];

    const int w    = threadIdx.x >> 5;
    const int lane = threadIdx.x & 31;
    const int dcol = blockIdx.x * SLICE + lane;   // this thread's global dim

    for (int i = threadIdx.x; i < ACC_WARPS * C * SLICE; i += blockDim.x)
        ((float*)acc)[i] = 0.0f;
    __syncthreads();

    const int is64 = g_label_is_i64;
    const int r0 = blockIdx.y * rows_per_block;
    const int r1 = min(r0 + rows_per_block, N);

    float* __restrict__ myacc = &acc[w][0][0];
    const int step = ACC_WARPS;

    int r = r0 + w;
    // 4x unroll: front-batch loads for MLP, independent RMW chains
    for (; r + 3 * step < r1; r += 4 * step) {
        const int i0 = r, i1 = r + step, i2 = r + 2 * step, i3 = r + 3 * step;
        const int la = load_label(l32, i0, is64);
        const int lb = load_label(l32, i1, is64);
        const int lc = load_label(l32, i2, is64);
        const int ld = load_label(l32, i3, is64);
        const float va = feat[(size_t)i0 * D + dcol];
        const float vb = feat[(size_t)i1 * D + dcol];
        const float vc = feat[(size_t)i2 * D + dcol];
        const float vd = feat[(size_t)i3 * D + dcol];
        myacc[la * SLICE + lane] += va;
        myacc[lb * SLICE + lane] += vb;
        myacc[lc * SLICE + lane] += vc;
        myacc[ld * SLICE + lane] += vd;
    }
    for (; r < r1; r += step) {
        const int la = load_label(l32, r, is64);
        const float va = feat[(size_t)r * D + dcol];
        myacc[la * SLICE + lane] += va;
    }
    __syncthreads();

    // reduce the warp copies, flush with atomics (148 contenders per address)
    const int dbase = blockIdx.x * SLICE;
    for (int i = threadIdx.x; i < C * SLICE; i += blockDim.x) {
        float s = 0.0f;
        #pragma unroll
        for (int ww = 0; ww < ACC_WARPS; ww++) s += (&acc[ww][0][0])[i];
        const int cls = i / SLICE;
        const int dd  = i - cls * SLICE;
        atomicAdd(&g_sums[cls * D + dbase + dd], s);
    }
}

// ---------------------------------------------------------------------------
// Kernel 4: centers = sums / counts
// ---------------------------------------------------------------------------
__global__ void k_finalize() {
    int i = blockIdx.x * blockDim.x + threadIdx.x;
    if (i < C * D) {
        float cnt = g_counts[i / D];
        g_centers[i] = (cnt > 0.0f) ? g_sums[i] / cnt : 0.0f;
    }
}

// ---------------------------------------------------------------------------
// Kernel 5: per-row distance to own-class center. One warp per row.
// Lane reads 2x float4 (8 dims), warp shfl-reduce, lane 0 writes sqrt.
// Centers (100KB) stay L2/L1 resident.
// ---------------------------------------------------------------------------
__global__ void __launch_bounds__(256)
k_dist(const float* __restrict__ feat, const int* __restrict__ l32,
       float* __restrict__ out, int N) {
    const int warp = (int)((blockIdx.x * blockDim.x + threadIdx.x) >> 5);
    const int lane = threadIdx.x & 31;
    if (warp >= N) return;

    const int is64 = g_label_is_i64;
    const int lab = load_label(l32, warp, is64);

    const float4* __restrict__ f4 = (const float4*)(feat + (size_t)warp * D);
    const float4* __restrict__ c4 = (const float4*)(g_centers + (size_t)lab * D);

    const float4 fa = f4[lane];
    const float4 fb = f4[lane + 32];
    const float4 ca = c4[lane];
    const float4 cb = c4[lane + 32];

    float s = 0.0f, dx;
    dx = fa.x - ca.x; s = fmaf(dx, dx, s);
    dx = fa.y - ca.y; s = fmaf(dx, dx, s);
    dx = fa.z - ca.z; s = fmaf(dx, dx, s);
    dx = fa.w - ca.w; s = fmaf(dx, dx, s);
    dx = fb.x - cb.x; s = fmaf(dx, dx, s);
    dx = fb.y - cb.y; s = fmaf(dx, dx, s);
    dx = fb.z - cb.z; s = fmaf(dx, dx, s);
    dx = fb.w - cb.w; s = fmaf(dx, dx, s);

    #pragma unroll
    for (int o = 16; o; o >>= 1) s += __shfl_xor_sync(0xffffffffu, s, o);

    if (lane == 0) out[warp] = sqrtf(s);
}

// ---------------------------------------------------------------------------
extern "C" void kernel_launch(void* const* d_in, const int* in_sizes, int n_in,
                              void* d_out, int out_size) {
    const float* feat = (const float*)d_in[0];
    const int*   l32  = (const int*)d_in[1];   // int32 view; stride decided on device
    float* out = (float*)d_out;

    const int N = in_sizes[0] / D;             // 500000

    k_zero<<<(C * D + 255) / 256, 256>>>();
    {
        int pairs = N / 2;
        k_detect<<<(pairs + 255) / 256, 256>>>((const unsigned int*)l32, N);
    }
    k_count<<<100, 256>>>(l32, N);

    {
        int rpb = (N + GY - 1) / GY;
        dim3 grid(NSLICES, GY);
        k_accum<<<grid, ACC_WARPS * 32>>>(feat, l32, N, rpb);
    }

    k_finalize<<<(C * D + 255) / 256, 256>>>();

    {
        int rows_per_block = 256 / 32;         // 8 warps -> 8 rows per block
        int blocks = (N + rows_per_block - 1) / rows_per_block;
        k_dist<<<blocks, 256>>>(feat, l32, out, N);
    }
}

// round 2
// speedup vs baseline: 1.1714x; 1.1714x over previous
#include <cuda_runtime.h>
#include <math.h>

#define C 100          // number of classes (static in reference)
#define D 256          // feature dim
#define SLICE 32       // dims handled per warp in accumulate pass
#define NSLICES (D / SLICE)   // 8
#define ACC_WARPS 2    // warps per accumulate block (smem = 2*100*32*4 = 25.6KB)
#define GY 148         // row chunks -> 8*148 = 1184 blocks = 1 wave at 8 blocks/SM
#define BATCH 16       // rows per pipelined register batch (per warp)

__device__ float g_sums[C * D];
__device__ float g_counts[C];
__device__ float g_centers[C * D];
__device__ int   g_label_is_i64;   // 1 => labels are int64 (stride-2 int32 words)

// ---------------------------------------------------------------------------
// Kernel 0: zero scratch + init dtype flag (assume int64 until proven int32)
// ---------------------------------------------------------------------------
__global__ void k_zero() {
    int i = blockIdx.x * blockDim.x + threadIdx.x;
    if (i < C * D) g_sums[i] = 0.0f;
    if (i < C)     g_counts[i] = 0.0f;
    if (i == 0)    g_label_is_i64 = 1;
}

// ---------------------------------------------------------------------------
// Kernel 1: dtype detect. If labels are little-endian int64 (<2^31), every odd
// 32-bit word is zero. If int32, odd words hold labels (uniform 0..99) and are
// nonzero somewhere among 250K samples with certainty.
// ---------------------------------------------------------------------------
__global__ void k_detect(const unsigned int* __restrict__ lw, int nwords) {
    int i = blockIdx.x * blockDim.x + threadIdx.x;
    int idx = 2 * i + 1;
    if (idx < nwords && lw[idx] != 0u) g_label_is_i64 = 0;
}

__device__ __forceinline__ int load_label(const int* __restrict__ l32, int i, int is64) {
    return __ldg(&l32[is64 ? (i << 1) : i]);
}

// ---------------------------------------------------------------------------
// Kernel 2: segment-sum of feat into g_sums (+ fused label histogram on the
// slice-0 blocks).
// Grid: (NSLICES, GY). Block: 64 threads = 2 warps. Each warp owns a private
// smem accumulator acc[warp][C][SLICE]; lane l handles dim slice*32 + l.
// Bank index = (class*32 + l) % 32 = l  -> conflict-free RMW.
//
// Software pipeline: double-buffered register batches of BATCH rows. Loads for
// batch k+1 are issued before the RMW chain of batch k, keeping 16 feat lines
// (2 KB) in flight per warp -> 32 KB/SM -> HBM-saturating MLP.
// ---------------------------------------------------------------------------
__global__ void __launch_bounds__(ACC_WARPS * 32)
k_accum(const float* __restrict__ feat, const int* __restrict__ l32,
        int N, int rows_per_block) {
    __shared__ float acc[ACC_WARPS][C][SLICE];
    __shared__ int   hist[C];

    const int w    = threadIdx.x >> 5;
    const int lane = threadIdx.x & 31;
    const int dcol = blockIdx.x * SLICE + lane;   // this thread's global dim

    for (int i = threadIdx.x; i < ACC_WARPS * C * SLICE; i += blockDim.x)
        ((float*)acc)[i] = 0.0f;
    if (blockIdx.x == 0)
        for (int i = threadIdx.x; i < C; i += blockDim.x) hist[i] = 0;
    __syncthreads();

    const int is64 = g_label_is_i64;
    const int r0 = blockIdx.y * rows_per_block;
    const int r1 = min(r0 + rows_per_block, N);

    float* __restrict__ myacc = &acc[w][0][0];
    const int step = ACC_WARPS;
    const int first = r0 + w;
    const int cnt = (r1 > first) ? (r1 - first + step - 1) / step : 0;
    const int nb  = cnt / BATCH;          // full register batches

    float vA[BATCH], vB[BATCH];
    int   lA[BATCH], lB[BATCH];

#define LOADB(V, L, RBASE)                                                    \
    {                                                                         \
        const int _rb = (RBASE);                                              \
        _Pragma("unroll")                                                     \
        for (int j = 0; j < BATCH; j++) {                                     \
            const int rr = _rb + j * step;                                    \
            (L)[j] = load_label(l32, rr, is64);                               \
            (V)[j] = __ldg(&feat[(size_t)rr * D + dcol]);                     \
        }                                                                     \
    }

#define RMWB(V, L)                                                            \
    {                                                                         \
        _Pragma("unroll")                                                     \
        for (int j = 0; j < BATCH; j++)                                       \
            myacc[(L)[j] * SLICE + lane] += (V)[j];                           \
    }

    if (nb > 0) {
        LOADB(vA, lA, first);
        int b = 1;
        for (; b + 1 < nb; b += 2) {
            LOADB(vB, lB, first + b * BATCH * step);
            RMWB(vA, lA);
            LOADB(vA, lA, first + (b + 1) * BATCH * step);
            RMWB(vB, lB);
        }
        if (b < nb) {
            LOADB(vB, lB, first + b * BATCH * step);
            RMWB(vA, lA);
            RMWB(vB, lB);
        } else {
            RMWB(vA, lA);
        }
    }
    // tail rows
    for (int rr = first + nb * BATCH * step; rr < r1; rr += step) {
        const int la = load_label(l32, rr, is64);
        myacc[la * SLICE + lane] += __ldg(&feat[(size_t)rr * D + dcol]);
    }

#undef LOADB
#undef RMWB

    // fused label histogram (only one slice counts each row)
    if (blockIdx.x == 0) {
        for (int i = r0 + threadIdx.x; i < r1; i += blockDim.x)
            atomicAdd(&hist[load_label(l32, i, is64)], 1);
    }
    __syncthreads();

    // reduce the warp copies, flush with atomics (148 contenders per address)
    const int dbase = blockIdx.x * SLICE;
    for (int i = threadIdx.x; i < C * SLICE; i += blockDim.x) {
        float s = 0.0f;
        #pragma unroll
        for (int ww = 0; ww < ACC_WARPS; ww++) s += (&acc[ww][0][0])[i];
        const int cls = i / SLICE;
        const int dd  = i - cls * SLICE;
        atomicAdd(&g_sums[cls * D + dbase + dd], s);
    }
    if (blockIdx.x == 0) {
        for (int i = threadIdx.x; i < C; i += blockDim.x)
            if (hist[i]) atomicAdd(&g_counts[i], (float)hist[i]);
    }
}

// ---------------------------------------------------------------------------
// Kernel 3: centers = sums / counts
// ---------------------------------------------------------------------------
__global__ void k_finalize() {
    int i = blockIdx.x * blockDim.x + threadIdx.x;
    if (i < C * D) {
        float cnt = g_counts[i / D];
        g_centers[i] = (cnt > 0.0f) ? g_sums[i] / cnt : 0.0f;
    }
}

// ---------------------------------------------------------------------------
// Kernel 4: per-row distance to own-class center. One warp per row.
// Lane reads 2x float4 (8 dims), warp shfl-reduce, lane 0 writes sqrt.
// Centers (100KB) stay L2/L1 resident.
// ---------------------------------------------------------------------------
__global__ void __launch_bounds__(256)
k_dist(const float* __restrict__ feat, const int* __restrict__ l32,
       float* __restrict__ out, int N) {
    const int warp = (int)((blockIdx.x * blockDim.x + threadIdx.x) >> 5);
    const int lane = threadIdx.x & 31;
    if (warp >= N) return;

    const int is64 = g_label_is_i64;
    const int lab = load_label(l32, warp, is64);

    const float4* __restrict__ f4 = (const float4*)(feat + (size_t)warp * D);
    const float4* __restrict__ c4 = (const float4*)(g_centers + (size_t)lab * D);

    const float4 fa = __ldcs(&f4[lane]);        // streaming: don't pollute L2
    const float4 fb = __ldcs(&f4[lane + 32]);
    const float4 ca = __ldg(&c4[lane]);
    const float4 cb = __ldg(&c4[lane + 32]);

    float s = 0.0f, dx;
    dx = fa.x - ca.x; s = fmaf(dx, dx, s);
    dx = fa.y - ca.y; s = fmaf(dx, dx, s);
    dx = fa.z - ca.z; s = fmaf(dx, dx, s);
    dx = fa.w - ca.w; s = fmaf(dx, dx, s);
    dx = fb.x - cb.x; s = fmaf(dx, dx, s);
    dx = fb.y - cb.y; s = fmaf(dx, dx, s);
    dx = fb.z - cb.z; s = fmaf(dx, dx, s);
    dx = fb.w - cb.w; s = fmaf(dx, dx, s);

    #pragma unroll
    for (int o = 16; o; o >>= 1) s += __shfl_xor_sync(0xffffffffu, s, o);

    if (lane == 0) out[warp] = sqrtf(s);
}

// ---------------------------------------------------------------------------
extern "C" void kernel_launch(void* const* d_in, const int* in_sizes, int n_in,
                              void* d_out, int out_size) {
    const float* feat = (const float*)d_in[0];
    const int*   l32  = (const int*)d_in[1];   // int32 view; stride decided on device
    float* out = (float*)d_out;

    const int N = in_sizes[0] / D;             // 500000

    k_zero<<<(C * D + 255) / 256, 256>>>();
    {
        int pairs = N / 2;
        k_detect<<<(pairs + 255) / 256, 256>>>((const unsigned int*)l32, N);
    }
    {
        int rpb = (N + GY - 1) / GY;
        dim3 grid(NSLICES, GY);
        k_accum<<<grid, ACC_WARPS * 32>>>(feat, l32, N, rpb);
    }
    k_finalize<<<(C * D + 255) / 256, 256>>>();
    {
        int rows_per_block = 256 / 32;         // 8 warps -> 8 rows per block
        int blocks = (N + rows_per_block - 1) / rows_per_block;
        k_dist<<<blocks, 256>>>(feat, l32, out, N);
    }
}